// round 1
// baseline (speedup 1.0000x reference)
#include <cuda_runtime.h>
#include <math.h>

// DBN beat decoder (bar-pointer Viterbi), exact replication of reference arithmetic.
// B=4, T=6000, intervals tau=28..109 (82 blocks), S=5617 states.
//
// One CTA per batch. delta kept in shared memory (double buffered).
// Per step: (1) 82x82 max-plus reduction for from_beat (no argmax tracking),
//           (2) shift + emission add for all states.
// Backpointers compressed: only the 82 prev_last floats per step are stored
// (bp = s-1 everywhere except first-states); argmax is recomputed during
// backtracking only at beat jumps (~90 per batch), with identical candidates
// and first-index tiebreak => bit-identical path to the reference.

#define NI      82
#define MINTAU  28
#define NSTATE  5617
#define TT      6000
#define BB      4
#define NTHREADS 1024
#define NSLOTS  6     // ceil(5617/1024)

// prev_last rows per step: g_plbuf[b][t][i] = delta(t-1)[last_idx[i]] (rows used for t=1..5999)
__device__ float g_plbuf[BB][TT][NI];

__device__ __forceinline__ int base_of(int j) {
    // base(j) = sum_{i<j} (28+i) = 28j + j(j-1)/2
    return MINTAU * j + (j * (j - 1)) / 2;
}

__global__ void __launch_bounds__(NTHREADS, 1)
dbn_viterbi_kernel(const float* __restrict__ logit, float* __restrict__ out)
{
    extern __shared__ float sm[];
    float* sm_delta = sm;                       // 2 * 5632
    float* sm_tl    = sm_delta + 2 * 5632;      // 82*82 = 6724
    float* sm_blp   = sm_tl + NI * NI;          // 6000
    float* sm_nblp  = sm_blp + TT;              // 6000
    float* sm_pl    = sm_nblp + TT;             // 128
    float* sm_fb    = sm_pl + 128;              // 128
    float* sm_rv    = sm_fb + 128;              // 1024
    int*   sm_ri    = (int*)(sm_rv + NTHREADS); // 1024

    const int tid = threadIdx.x;
    const int b   = blockIdx.x;
    const float* lg = logit + b * TT;
    float* outrow   = out + b * TT;

    // ---- zero output row (harness poisons d_out) ----
    for (int t = tid; t < TT; t += NTHREADS) outrow[t] = 0.0f;

    // ---- emissions: log_sigmoid(x), log_sigmoid(-x) in double, cast to f32 ----
    for (int t = tid; t < TT; t += NTHREADS) {
        double x = (double)lg[t];
        double bl = (x >= 0.0) ? -log1p(exp(-x)) : (x - log1p(exp(x)));
        double nl = (x <= 0.0) ? -log1p(exp(x))  : (-x - log1p(exp(-x)));
        sm_blp[t]  = (float)bl;
        sm_nblp[t] = (float)nl;
    }

    // ---- trans_log (log-softmax of -100*|tau_j/tau_i - 1| per row, double precision) ----
    if (tid < NI) {
        int i = tid;
        double ti = (double)(MINTAU + i);
        double ssum = 0.0;
        for (int j = 0; j < NI; ++j) {
            double r = -100.0 * fabs((double)(MINTAU + j) / ti - 1.0);
            ssum += exp(r);
        }
        double ls = log(ssum);  // row max is 0 (at j==i), so log-sum-exp = log(sum)
        for (int j = 0; j < NI; ++j) {
            double r = -100.0 * fabs((double)(MINTAU + j) / ti - 1.0);
            sm_tl[i * NI + j] = (float)(r - ls);
        }
    }

    // ---- per-thread slot metadata (states s = tid + k*1024) ----
    int  slotPrev[NSLOTS];
    int  slotBlk[NSLOTS];
    bool slotFirst[NSLOTS], slotLast[NSLOTS], slotValid[NSLOTS];
    #pragma unroll
    for (int k = 0; k < NSLOTS; ++k) {
        int s = tid + k * NTHREADS;
        bool v = (s < NSTATE);
        slotValid[k] = v;
        int j = 0;
        if (v) { while (base_of(j + 1) <= s) ++j; }
        slotBlk[k]   = j;
        slotFirst[k] = v && (s == base_of(j));
        slotLast[k]  = v && (s == base_of(j + 1) - 1);
        slotPrev[k]  = (s == 0) ? 0 : (s - 1);
    }

    const float logS = (float)log((double)NSTATE);
    const float NEGINF = __int_as_float(0xff800000);

    float* cur = sm_delta;
    float* nxt = sm_delta + 5632;

    __syncthreads();  // emissions + trans_log ready

    // ---- init delta0 = emission(t=0) - log(S); publish prev_last ----
    #pragma unroll
    for (int k = 0; k < NSLOTS; ++k) {
        if (slotValid[k]) {
            int s = tid + k * NTHREADS;
            float em = slotFirst[k] ? sm_blp[0] : sm_nblp[0];
            float v = em - logS;
            cur[s] = v;
            if (slotLast[k]) sm_pl[slotBlk[k]] = v;
        }
    }

    // ---- forward Viterbi ----
    for (int t = 1; t < TT; ++t) {
        __syncthreads();  // cur & pl ready
        if (tid < 672) {  // warps 0..20 fully: 82 j-groups * 8 lanes, padded to 84 groups
            int j = tid >> 3, g = tid & 7;
            float best = NEGINF;
            if (j < NI) {
                #pragma unroll
                for (int k2 = 0; k2 < 11; ++k2) {
                    int i = g + (k2 << 3);
                    if (i < NI) best = fmaxf(best, sm_pl[i] + sm_tl[i * NI + j]);
                }
            }
            best = fmaxf(best, __shfl_xor_sync(0xffffffffu, best, 1));
            best = fmaxf(best, __shfl_xor_sync(0xffffffffu, best, 2));
            best = fmaxf(best, __shfl_xor_sync(0xffffffffu, best, 4));
            if (g == 0 && j < NI) sm_fb[j] = best;
        } else if (tid < 672 + NI) {
            // persist prev_last row for deferred backpointer recomputation
            g_plbuf[b][t][tid - 672] = sm_pl[tid - 672];
        }
        __syncthreads();  // fb ready
        float bt  = sm_blp[t];
        float nbt = sm_nblp[t];
        #pragma unroll
        for (int k = 0; k < NSLOTS; ++k) {
            if (slotValid[k]) {
                int s = tid + k * NTHREADS;
                float v = cur[slotPrev[k]] + nbt;               // shift + nonbeat emission
                if (slotFirst[k]) v = sm_fb[slotBlk[k]] + bt;   // beat entry
                nxt[s] = v;
                if (slotLast[k]) sm_pl[slotBlk[k]] = v;
            }
        }
        float* tmp = cur; cur = nxt; nxt = tmp;
    }

    // ---- final argmax over delta(T-1) (first-index tiebreak) ----
    __syncthreads();
    {
        float bv = NEGINF; int bs = 0x7fffffff;
        for (int s = tid; s < NSTATE; s += NTHREADS) {
            float v = cur[s];
            if (v > bv) { bv = v; bs = s; }
        }
        sm_rv[tid] = bv; sm_ri[tid] = bs;
    }
    __syncthreads();
    for (int st = NTHREADS >> 1; st > 0; st >>= 1) {
        if (tid < st) {
            float v2 = sm_rv[tid + st]; int s2 = sm_ri[tid + st];
            if (v2 > sm_rv[tid] || (v2 == sm_rv[tid] && s2 < sm_ri[tid])) {
                sm_rv[tid] = v2; sm_ri[tid] = s2;
            }
        }
        __syncthreads();
    }

    // ---- backtrack (thread 0): jump beat-to-beat, ~90 hops ----
    if (tid == 0) {
        // threshold in logit space for sigmoid(x) >= 0.05f
        const double p0  = (double)0.05f;
        const double thr = log(p0 / (1.0 - p0));

        int s = sm_ri[0];
        int j = 0;
        while (base_of(j + 1) <= s) ++j;
        int p = s - base_of(j);
        int t = TT - 1;
        while (true) {
            if (p > t) break;          // path started mid-block at t=0: no beat
            int tb = t - p;            // beat time (position 0)
            double x = (double)lg[tb];
            outrow[tb] = (x >= thr) ? 1.0f : 0.0f;
            if (tb == 0) break;
            // recompute argmax_i pl[i] + tl[i][j] at step tb (first-index tiebreak)
            const float* row = &g_plbuf[b][tb][0];
            float mx = NEGINF; int bi = 0;
            for (int i = 0; i < NI; ++i) {
                float c = row[i] + sm_tl[i * NI + j];
                if (c > mx) { mx = c; bi = i; }
            }
            j = bi;
            t = tb - 1;
            p = (MINTAU + j) - 1;      // last position of block j
        }
    }
}

extern "C" void kernel_launch(void* const* d_in, const int* in_sizes, int n_in,
                              void* d_out, int out_size)
{
    const float* logit = (const float*)d_in[0];
    float* out = (float*)d_out;

    // floats: 2*5632 + 6724 + 6000 + 6000 + 128 + 128 + 1024 + 1024 = 32292
    size_t smem = 32292u * sizeof(float);
    cudaFuncSetAttribute(dbn_viterbi_kernel,
                         cudaFuncAttributeMaxDynamicSharedMemorySize, (int)smem);
    dbn_viterbi_kernel<<<BB, NTHREADS, smem>>>(logit, out);
}

// round 2
// speedup vs baseline: 1.0037x; 1.0037x over previous
#include <cuda_runtime.h>
#include <math.h>

// DBN beat decoder (bar-pointer Viterbi), exact replication of reference arithmetic.
// B=4, T=6000, intervals tau=28..109 (82 blocks), S=5617 states.
//
// One CTA per batch. delta kept in shared memory (double buffered).
// Per step: (1) 82x82 max-plus reduction for from_beat (no argmax tracking),
//           (2) shift + emission add for all states.
// Backpointers compressed: only the 82 prev_last floats per step are stored
// (bp = s-1 everywhere except first-states); argmax is recomputed during
// backtracking only at beat jumps (~90 per batch), with identical candidates
// and first-index tiebreak => bit-identical path to the reference.

#define NI      82
#define MINTAU  28
#define NSTATE  5617
#define TT      6000
#define BB      4
#define NTHREADS 1024
#define NSLOTS  6     // ceil(5617/1024)

// prev_last rows per step: g_plbuf[b][t][i] = delta(t-1)[last_idx[i]] (rows used for t=1..5999)
__device__ float g_plbuf[BB][TT][NI];

__device__ __forceinline__ int base_of(int j) {
    // base(j) = sum_{i<j} (28+i) = 28j + j(j-1)/2
    return MINTAU * j + (j * (j - 1)) / 2;
}

__global__ void __launch_bounds__(NTHREADS, 1)
dbn_viterbi_kernel(const float* __restrict__ logit, float* __restrict__ out)
{
    extern __shared__ float sm[];
    float* sm_delta = sm;                       // 2 * 5632
    float* sm_tl    = sm_delta + 2 * 5632;      // 82*82 = 6724
    float* sm_blp   = sm_tl + NI * NI;          // 6000
    float* sm_nblp  = sm_blp + TT;              // 6000
    float* sm_pl    = sm_nblp + TT;             // 128
    float* sm_fb    = sm_pl + 128;              // 128
    float* sm_rv    = sm_fb + 128;              // 1024
    int*   sm_ri    = (int*)(sm_rv + NTHREADS); // 1024

    const int tid = threadIdx.x;
    const int b   = blockIdx.x;
    const float* lg = logit + b * TT;
    float* outrow   = out + b * TT;

    // ---- zero output row (harness poisons d_out) ----
    for (int t = tid; t < TT; t += NTHREADS) outrow[t] = 0.0f;

    // ---- emissions: log_sigmoid(x), log_sigmoid(-x) in double, cast to f32 ----
    for (int t = tid; t < TT; t += NTHREADS) {
        double x = (double)lg[t];
        double bl = (x >= 0.0) ? -log1p(exp(-x)) : (x - log1p(exp(x)));
        double nl = (x <= 0.0) ? -log1p(exp(x))  : (-x - log1p(exp(-x)));
        sm_blp[t]  = (float)bl;
        sm_nblp[t] = (float)nl;
    }

    // ---- trans_log (log-softmax of -100*|tau_j/tau_i - 1| per row, double precision) ----
    if (tid < NI) {
        int i = tid;
        double ti = (double)(MINTAU + i);
        double ssum = 0.0;
        for (int j = 0; j < NI; ++j) {
            double r = -100.0 * fabs((double)(MINTAU + j) / ti - 1.0);
            ssum += exp(r);
        }
        double ls = log(ssum);  // row max is 0 (at j==i), so log-sum-exp = log(sum)
        for (int j = 0; j < NI; ++j) {
            double r = -100.0 * fabs((double)(MINTAU + j) / ti - 1.0);
            sm_tl[i * NI + j] = (float)(r - ls);
        }
    }

    // ---- per-thread slot metadata (states s = tid + k*1024) ----
    int  slotPrev[NSLOTS];
    int  slotBlk[NSLOTS];
    bool slotFirst[NSLOTS], slotLast[NSLOTS], slotValid[NSLOTS];
    #pragma unroll
    for (int k = 0; k < NSLOTS; ++k) {
        int s = tid + k * NTHREADS;
        bool v = (s < NSTATE);
        slotValid[k] = v;
        int j = 0;
        if (v) { while (base_of(j + 1) <= s) ++j; }
        slotBlk[k]   = j;
        slotFirst[k] = v && (s == base_of(j));
        slotLast[k]  = v && (s == base_of(j + 1) - 1);
        slotPrev[k]  = (s == 0) ? 0 : (s - 1);
    }

    const float logS = (float)log((double)NSTATE);
    const float NEGINF = __int_as_float(0xff800000);

    float* cur = sm_delta;
    float* nxt = sm_delta + 5632;

    __syncthreads();  // emissions + trans_log ready

    // ---- init delta0 = emission(t=0) - log(S); publish prev_last ----
    #pragma unroll
    for (int k = 0; k < NSLOTS; ++k) {
        if (slotValid[k]) {
            int s = tid + k * NTHREADS;
            float em = slotFirst[k] ? sm_blp[0] : sm_nblp[0];
            float v = em - logS;
            cur[s] = v;
            if (slotLast[k]) sm_pl[slotBlk[k]] = v;
        }
    }

    // ---- forward Viterbi ----
    for (int t = 1; t < TT; ++t) {
        __syncthreads();  // cur & pl ready
        if (tid < 672) {  // warps 0..20 fully: 82 j-groups * 8 lanes, padded to 84 groups
            int j = tid >> 3, g = tid & 7;
            float best = NEGINF;
            if (j < NI) {
                #pragma unroll
                for (int k2 = 0; k2 < 11; ++k2) {
                    int i = g + (k2 << 3);
                    if (i < NI) best = fmaxf(best, sm_pl[i] + sm_tl[i * NI + j]);
                }
            }
            best = fmaxf(best, __shfl_xor_sync(0xffffffffu, best, 1));
            best = fmaxf(best, __shfl_xor_sync(0xffffffffu, best, 2));
            best = fmaxf(best, __shfl_xor_sync(0xffffffffu, best, 4));
            if (g == 0 && j < NI) sm_fb[j] = best;
        } else if (tid < 672 + NI) {
            // persist prev_last row for deferred backpointer recomputation
            g_plbuf[b][t][tid - 672] = sm_pl[tid - 672];
        }
        __syncthreads();  // fb ready
        float bt  = sm_blp[t];
        float nbt = sm_nblp[t];
        #pragma unroll
        for (int k = 0; k < NSLOTS; ++k) {
            if (slotValid[k]) {
                int s = tid + k * NTHREADS;
                float v = cur[slotPrev[k]] + nbt;               // shift + nonbeat emission
                if (slotFirst[k]) v = sm_fb[slotBlk[k]] + bt;   // beat entry
                nxt[s] = v;
                if (slotLast[k]) sm_pl[slotBlk[k]] = v;
            }
        }
        float* tmp = cur; cur = nxt; nxt = tmp;
    }

    // ---- final argmax over delta(T-1) (first-index tiebreak) ----
    __syncthreads();
    {
        float bv = NEGINF; int bs = 0x7fffffff;
        for (int s = tid; s < NSTATE; s += NTHREADS) {
            float v = cur[s];
            if (v > bv) { bv = v; bs = s; }
        }
        sm_rv[tid] = bv; sm_ri[tid] = bs;
    }
    __syncthreads();
    for (int st = NTHREADS >> 1; st > 0; st >>= 1) {
        if (tid < st) {
            float v2 = sm_rv[tid + st]; int s2 = sm_ri[tid + st];
            if (v2 > sm_rv[tid] || (v2 == sm_rv[tid] && s2 < sm_ri[tid])) {
                sm_rv[tid] = v2; sm_ri[tid] = s2;
            }
        }
        __syncthreads();
    }

    // ---- backtrack (thread 0): jump beat-to-beat, ~90 hops ----
    if (tid == 0) {
        // threshold in logit space for sigmoid(x) >= 0.05f
        const double p0  = (double)0.05f;
        const double thr = log(p0 / (1.0 - p0));

        int s = sm_ri[0];
        int j = 0;
        while (base_of(j + 1) <= s) ++j;
        int p = s - base_of(j);
        int t = TT - 1;
        while (true) {
            if (p > t) break;          // path started mid-block at t=0: no beat
            int tb = t - p;            // beat time (position 0)
            double x = (double)lg[tb];
            outrow[tb] = (x >= thr) ? 1.0f : 0.0f;
            if (tb == 0) break;
            // recompute argmax_i pl[i] + tl[i][j] at step tb (first-index tiebreak)
            const float* row = &g_plbuf[b][tb][0];
            float mx = NEGINF; int bi = 0;
            for (int i = 0; i < NI; ++i) {
                float c = row[i] + sm_tl[i * NI + j];
                if (c > mx) { mx = c; bi = i; }
            }
            j = bi;
            t = tb - 1;
            p = (MINTAU + j) - 1;      // last position of block j
        }
    }
}

extern "C" void kernel_launch(void* const* d_in, const int* in_sizes, int n_in,
                              void* d_out, int out_size)
{
    const float* logit = (const float*)d_in[0];
    float* out = (float*)d_out;

    // floats: 2*5632 + 6724 + 6000 + 6000 + 128 + 128 + 1024 + 1024 = 32292
    size_t smem = 32292u * sizeof(float);
    cudaFuncSetAttribute(dbn_viterbi_kernel,
                         cudaFuncAttributeMaxDynamicSharedMemorySize, (int)smem);
    dbn_viterbi_kernel<<<BB, NTHREADS, smem>>>(logit, out);
}